// round 5
// baseline (speedup 1.0000x reference)
#include <cuda_runtime.h>

// ---------------------------------------------------------------------------
// TinyGPT forward, fp32 SIMT (128x128 double-buffered SGEMM + flash attention)
// B=2, T=2048 (NV=256 vision + 1792 text), D=1024, H=16, DH=64, L=8,
// DFF=4096, VOCAB=32000. Output: fp32 logits [2, 1792, 32000].
// ---------------------------------------------------------------------------

#define TSEQ   2048
#define NVTOK  256
#define TTEXT  1792
#define DMODEL 1024
#define DFFDIM 4096
#define NHEAD  16
#define DHEAD  64
#define NLAYER 8
#define VOCABN 32000
#define BROWS  (2 * TSEQ)    // 4096 total token rows
#define MTEXT  (2 * TTEXT)   // 3584 text rows

// ------------------------- scratch (device globals) ------------------------
__device__ float g_x  [BROWS * DMODEL];       // residual stream
__device__ float g_h  [BROWS * DMODEL];       // LN output
__device__ float g_qkv[BROWS * 3 * DMODEL];   // fused QKV
__device__ float g_att[BROWS * DMODEL];       // attention output (concat heads)
__device__ float g_ff [BROWS * DFFDIM];       // fc1 output
__device__ float g_hc [MTEXT * DMODEL];       // final LN (text rows only)

// ------------------------------- embedding ---------------------------------
__global__ __launch_bounds__(256)
void embed_kernel(const int* __restrict__ idx, const float* __restrict__ img,
                  const float* __restrict__ tok, const float* __restrict__ pos,
                  float* __restrict__ x)
{
    int i = blockIdx.x * 256 + threadIdx.x;       // over B*T*D/4
    int d4 = (i & 255) << 2;                      // 0..1020 step 4
    int t  = (i >> 8) & (TSEQ - 1);
    int b  = i >> 19;                             // /(256*2048)

    float4 base;
    if (t < NVTOK) {
        base = *(const float4*)(img + ((size_t)(b * NVTOK + t) * DMODEL) + d4);
    } else {
        int tid = idx[b * TTEXT + (t - NVTOK)];
        base = *(const float4*)(tok + (size_t)tid * DMODEL + d4);
    }
    float4 p = *(const float4*)(pos + (size_t)t * DMODEL + d4);
    base.x += p.x; base.y += p.y; base.z += p.z; base.w += p.w;
    *(float4*)(x + (size_t)(b * TSEQ + t) * DMODEL + d4) = base;
}

// ------------------------------- layernorm ---------------------------------
// One block per row, 256 threads, D=1024 (4 elems/thread).
// remap=1: row r maps to input row (r/TTEXT)*T + NV + r%TTEXT (text-only LNf).
__global__ __launch_bounds__(256)
void ln_kernel(const float* __restrict__ x, const float* __restrict__ w,
               const float* __restrict__ bias, float* __restrict__ out, int remap)
{
    __shared__ float sh1[8];
    __shared__ float sh2[8];
    int r = blockIdx.x;
    int rin = remap ? ((r / TTEXT) * TSEQ + NVTOK + (r % TTEXT)) : r;
    int tid = threadIdx.x;

    float4 v = *(const float4*)(x + (size_t)rin * DMODEL + (tid << 2));
    float s = v.x + v.y + v.z + v.w;
    #pragma unroll
    for (int o = 16; o > 0; o >>= 1) s += __shfl_xor_sync(0xffffffffu, s, o);
    if ((tid & 31) == 0) sh1[tid >> 5] = s;
    __syncthreads();
    float tot = sh1[0] + sh1[1] + sh1[2] + sh1[3] + sh1[4] + sh1[5] + sh1[6] + sh1[7];
    float mu = tot * (1.0f / DMODEL);

    float d0 = v.x - mu, d1 = v.y - mu, d2 = v.z - mu, d3 = v.w - mu;
    float ss = d0 * d0 + d1 * d1 + d2 * d2 + d3 * d3;
    #pragma unroll
    for (int o = 16; o > 0; o >>= 1) ss += __shfl_xor_sync(0xffffffffu, ss, o);
    if ((tid & 31) == 0) sh2[tid >> 5] = ss;
    __syncthreads();
    float tot2 = sh2[0] + sh2[1] + sh2[2] + sh2[3] + sh2[4] + sh2[5] + sh2[6] + sh2[7];
    float rs = rsqrtf(tot2 * (1.0f / DMODEL) + 1e-5f);

    float4 wv = *(const float4*)(w + (tid << 2));
    float4 bv = *(const float4*)(bias + (tid << 2));
    float4 o4;
    o4.x = d0 * rs * wv.x + bv.x;
    o4.y = d1 * rs * wv.y + bv.y;
    o4.z = d2 * rs * wv.z + bv.z;
    o4.w = d3 * rs * wv.w + bv.w;
    *(float4*)(out + (size_t)r * DMODEL + (tid << 2)) = o4;
}

// --------------------------------- GEMM ------------------------------------
// C[M,N] = A[M,K] @ W[N,K]^T (+ bias[n]) (+relu) (+ Res[m,n]).
// Tiles: BM=128, BN=128, BK=16. 256 threads, 8x8 microtile per thread
// (split 4+4 across the two 64-halves of each tile dimension).
// Double-buffered smem, register prefetch, one barrier per k-tile.
// Requires M%128==0, N%128==0, K%32==0 (true for all call sites).
template<bool BIAS, bool RELU, bool RES>
__global__ __launch_bounds__(256)
void gemm_kernel(const float* __restrict__ A, const float* __restrict__ W,
                 const float* __restrict__ bias, const float* __restrict__ Res,
                 float* __restrict__ C, int M, int N, int K)
{
    __shared__ float As[2][16][132];   // [buf][k][m], padded
    __shared__ float Ws[2][16][132];   // [buf][k][n], padded

    int n0 = blockIdx.x << 7;
    int m0 = blockIdx.y << 7;
    int tid = threadIdx.x;
    int tx = tid & 15, ty = tid >> 4;

    int arow = tid >> 1;            // 0..127
    int ak   = (tid & 1) << 3;      // 0 or 8
    const float* Ap = A + (size_t)(m0 + arow) * K + ak;
    const float* Wp = W + (size_t)(n0 + arow) * K + ak;

    float acc[8][8];
    #pragma unroll
    for (int i = 0; i < 8; i++)
        #pragma unroll
        for (int j = 0; j < 8; j++) acc[i][j] = 0.f;

    // preload tile 0 into buffer 0
    {
        float4 a0 = *(const float4*)(Ap);
        float4 a1 = *(const float4*)(Ap + 4);
        float4 w0 = *(const float4*)(Wp);
        float4 w1 = *(const float4*)(Wp + 4);
        As[0][ak + 0][arow] = a0.x; As[0][ak + 1][arow] = a0.y;
        As[0][ak + 2][arow] = a0.z; As[0][ak + 3][arow] = a0.w;
        As[0][ak + 4][arow] = a1.x; As[0][ak + 5][arow] = a1.y;
        As[0][ak + 6][arow] = a1.z; As[0][ak + 7][arow] = a1.w;
        Ws[0][ak + 0][arow] = w0.x; Ws[0][ak + 1][arow] = w0.y;
        Ws[0][ak + 2][arow] = w0.z; Ws[0][ak + 3][arow] = w0.w;
        Ws[0][ak + 4][arow] = w1.x; Ws[0][ak + 5][arow] = w1.y;
        Ws[0][ak + 6][arow] = w1.z; Ws[0][ak + 7][arow] = w1.w;
    }
    __syncthreads();

    int nk = K >> 4;
    for (int t = 0; t < nk; t++) {
        int cur = t & 1;
        // prefetch next tile into the other buffer (LDGs issue before the
        // FMA block; the barrier from last iteration guarantees nobody is
        // still reading buf cur^1)
        if (t + 1 < nk) {
            int kt = (t + 1) << 4;
            float4 a0 = *(const float4*)(Ap + kt);
            float4 a1 = *(const float4*)(Ap + kt + 4);
            float4 w0 = *(const float4*)(Wp + kt);
            float4 w1 = *(const float4*)(Wp + kt + 4);
            int nb = cur ^ 1;
            As[nb][ak + 0][arow] = a0.x; As[nb][ak + 1][arow] = a0.y;
            As[nb][ak + 2][arow] = a0.z; As[nb][ak + 3][arow] = a0.w;
            As[nb][ak + 4][arow] = a1.x; As[nb][ak + 5][arow] = a1.y;
            As[nb][ak + 6][arow] = a1.z; As[nb][ak + 7][arow] = a1.w;
            Ws[nb][ak + 0][arow] = w0.x; Ws[nb][ak + 1][arow] = w0.y;
            Ws[nb][ak + 2][arow] = w0.z; Ws[nb][ak + 3][arow] = w0.w;
            Ws[nb][ak + 4][arow] = w1.x; Ws[nb][ak + 5][arow] = w1.y;
            Ws[nb][ak + 6][arow] = w1.z; Ws[nb][ak + 7][arow] = w1.w;
        }

        #pragma unroll
        for (int k = 0; k < 16; k++) {
            float4 av0 = *(const float4*)&As[cur][k][ty << 2];
            float4 av1 = *(const float4*)&As[cur][k][(ty << 2) + 64];
            float4 bv0 = *(const float4*)&Ws[cur][k][tx << 2];
            float4 bv1 = *(const float4*)&Ws[cur][k][(tx << 2) + 64];
            float am[8] = {av0.x, av0.y, av0.z, av0.w, av1.x, av1.y, av1.z, av1.w};
            float bn[8] = {bv0.x, bv0.y, bv0.z, bv0.w, bv1.x, bv1.y, bv1.z, bv1.w};
            #pragma unroll
            for (int i = 0; i < 8; i++)
                #pragma unroll
                for (int j = 0; j < 8; j++)
                    acc[i][j] = fmaf(am[i], bn[j], acc[i][j]);
        }
        __syncthreads();
    }

    #pragma unroll
    for (int ih = 0; ih < 2; ih++) {
        #pragma unroll
        for (int ii = 0; ii < 4; ii++) {
            int m = m0 + (ih << 6) + (ty << 2) + ii;
            int ai = (ih << 2) + ii;
            #pragma unroll
            for (int jh = 0; jh < 2; jh++) {
                int n = n0 + (jh << 6) + (tx << 2);
                int aj = jh << 2;
                float4 v = make_float4(acc[ai][aj], acc[ai][aj + 1],
                                       acc[ai][aj + 2], acc[ai][aj + 3]);
                if (BIAS) {
                    float4 bv = *(const float4*)(bias + n);
                    v.x += bv.x; v.y += bv.y; v.z += bv.z; v.w += bv.w;
                }
                if (RELU) {
                    v.x = fmaxf(v.x, 0.f); v.y = fmaxf(v.y, 0.f);
                    v.z = fmaxf(v.z, 0.f); v.w = fmaxf(v.w, 0.f);
                }
                if (RES) {
                    float4 rv = *(const float4*)(Res + (size_t)m * N + n);
                    v.x += rv.x; v.y += rv.y; v.z += rv.z; v.w += rv.w;
                }
                *(float4*)(C + (size_t)m * N + n) = v;
            }
        }
    }
}

// ------------------------------- attention ---------------------------------
// Flash-style: block = (q-tile of 64, head, batch). K-tiles of 32.
// Text rows (q >= NV) are causal -> K-loop truncated at qt0+64.
__global__ __launch_bounds__(256)
void attn_kernel(const float* __restrict__ qkv, float* __restrict__ out)
{
    const int QKVD = 3 * DMODEL;
    int qt0 = blockIdx.x << 6;
    int h = blockIdx.y, b = blockIdx.z;
    int tid = threadIdx.x;
    int tx = tid & 15, ty = tid >> 4;
    int hoff = h * DHEAD;

    __shared__ float Qs[64][68];   // [d][m]
    __shared__ float Ks[64][36];   // [d][n]
    __shared__ float Vs[32][68];   // [n][d]
    __shared__ float Ss[32][68];   // [n][m]  (S^T, then P^T)
    __shared__ float mrow[64], lrow[64], alf[64];

    // load Q tile, transposed
    #pragma unroll
    for (int it = 0; it < 4; it++) {
        int idx = tid + it * 256;
        int row = idx >> 4;
        int d4 = (idx & 15) << 2;
        float4 v = *(const float4*)(qkv + (size_t)(b * TSEQ + qt0 + row) * QKVD + hoff + d4);
        Qs[d4 + 0][row] = v.x; Qs[d4 + 1][row] = v.y;
        Qs[d4 + 2][row] = v.z; Qs[d4 + 3][row] = v.w;
    }
    if (tid < 64) { mrow[tid] = -1e30f; lrow[tid] = 0.f; }

    float o[4][4];
    #pragma unroll
    for (int i = 0; i < 4; i++)
        #pragma unroll
        for (int j = 0; j < 4; j++) o[i][j] = 0.f;

    int ktend = (qt0 >= NVTOK) ? (qt0 + 64) : TSEQ;
    __syncthreads();

    for (int kt0 = 0; kt0 < ktend; kt0 += 32) {
        // load K (transposed) and V tiles
        #pragma unroll
        for (int it = 0; it < 2; it++) {
            int idx = tid + it * 256;
            int row = idx >> 4;
            int d4 = (idx & 15) << 2;
            const float* bp = qkv + (size_t)(b * TSEQ + kt0 + row) * QKVD + hoff + d4;
            float4 kv = *(const float4*)(bp + DMODEL);
            Ks[d4 + 0][row] = kv.x; Ks[d4 + 1][row] = kv.y;
            Ks[d4 + 2][row] = kv.z; Ks[d4 + 3][row] = kv.w;
            float4 vv = *(const float4*)(bp + 2 * DMODEL);
            *(float4*)&Vs[row][d4] = vv;
        }
        __syncthreads();

        // S = Q @ K^T : each thread 4 rows x 2 cols
        float s[4][2];
        #pragma unroll
        for (int i = 0; i < 4; i++) { s[i][0] = 0.f; s[i][1] = 0.f; }
        #pragma unroll
        for (int d = 0; d < 64; d++) {
            float4 a = *(const float4*)&Qs[d][ty << 2];
            float2 bb = *(const float2*)&Ks[d][tx << 1];
            s[0][0] = fmaf(a.x, bb.x, s[0][0]); s[0][1] = fmaf(a.x, bb.y, s[0][1]);
            s[1][0] = fmaf(a.y, bb.x, s[1][0]); s[1][1] = fmaf(a.y, bb.y, s[1][1]);
            s[2][0] = fmaf(a.z, bb.x, s[2][0]); s[2][1] = fmaf(a.z, bb.y, s[2][1]);
            s[3][0] = fmaf(a.w, bb.x, s[3][0]); s[3][1] = fmaf(a.w, bb.y, s[3][1]);
        }
        // mask + store S^T (scaled)
        #pragma unroll
        for (int j = 0; j < 2; j++) {
            int kg = kt0 + (tx << 1) + j;
            #pragma unroll
            for (int i = 0; i < 4; i++) {
                int qg = qt0 + (ty << 2) + i;
                bool ok = (qg < NVTOK) || (kg <= qg);
                Ss[(tx << 1) + j][(ty << 2) + i] = ok ? s[i][j] * 0.125f : -1e30f;
            }
        }
        __syncthreads();

        // online softmax per row
        if (tid < 64) {
            int m = tid;
            float mt = -1e30f;
            #pragma unroll
            for (int n = 0; n < 32; n++) mt = fmaxf(mt, Ss[n][m]);
            float mold = mrow[m];
            float mnew = fmaxf(mold, mt);
            float al = __expf(mold - mnew);
            float sum = 0.f;
            #pragma unroll
            for (int n = 0; n < 32; n++) {
                float p = __expf(Ss[n][m] - mnew);
                Ss[n][m] = p;
                sum += p;
            }
            mrow[m] = mnew;
            lrow[m] = lrow[m] * al + sum;
            alf[m] = al;
        }
        __syncthreads();

        // rescale accumulators, O += P @ V
        float av[4];
        #pragma unroll
        for (int i = 0; i < 4; i++) av[i] = alf[(ty << 2) + i];
        #pragma unroll
        for (int i = 0; i < 4; i++)
            #pragma unroll
            for (int j = 0; j < 4; j++) o[i][j] *= av[i];
        #pragma unroll
        for (int kk = 0; kk < 32; kk++) {
            float4 p = *(const float4*)&Ss[kk][ty << 2];
            float4 vv = *(const float4*)&Vs[kk][tx << 2];
            float pm[4] = {p.x, p.y, p.z, p.w};
            float vd[4] = {vv.x, vv.y, vv.z, vv.w};
            #pragma unroll
            for (int i = 0; i < 4; i++)
                #pragma unroll
                for (int j = 0; j < 4; j++)
                    o[i][j] = fmaf(pm[i], vd[j], o[i][j]);
        }
        __syncthreads();
    }

    #pragma unroll
    for (int i = 0; i < 4; i++) {
        int qg = qt0 + (ty << 2) + i;
        float inv = 1.f / lrow[(ty << 2) + i];
        float4 r = make_float4(o[i][0] * inv, o[i][1] * inv, o[i][2] * inv, o[i][3] * inv);
        *(float4*)(out + (size_t)(b * TSEQ + qg) * DMODEL + hoff + (tx << 2)) = r;
    }
}

// -------------------------------- launcher ---------------------------------
extern "C" void kernel_launch(void* const* d_in, const int* in_sizes, int n_in,
                              void* d_out, int out_size)
{
    (void)in_sizes; (void)n_in; (void)out_size;
    const int*   idx   = (const int*)  d_in[0];
    const float* img   = (const float*)d_in[1];
    const float* tok   = (const float*)d_in[2];
    const float* pos   = (const float*)d_in[3];
    const float* ln1w  = (const float*)d_in[4];
    const float* ln1b  = (const float*)d_in[5];
    const float* qkvw  = (const float*)d_in[6];
    const float* outw  = (const float*)d_in[7];
    const float* ln2w  = (const float*)d_in[8];
    const float* ln2b  = (const float*)d_in[9];
    const float* fc1w  = (const float*)d_in[10];
    const float* fc1b  = (const float*)d_in[11];
    const float* fc2w  = (const float*)d_in[12];
    const float* fc2b  = (const float*)d_in[13];
    const float* lnfw  = (const float*)d_in[14];
    const float* lnfb  = (const float*)d_in[15];
    const float* headw = (const float*)d_in[16];
    float* out = (float*)d_out;

    float *x, *h, *qkv, *att, *ff, *hc;
    cudaGetSymbolAddress((void**)&x,   g_x);
    cudaGetSymbolAddress((void**)&h,   g_h);
    cudaGetSymbolAddress((void**)&qkv, g_qkv);
    cudaGetSymbolAddress((void**)&att, g_att);
    cudaGetSymbolAddress((void**)&ff,  g_ff);
    cudaGetSymbolAddress((void**)&hc,  g_hc);

    embed_kernel<<<4096, 256>>>(idx, img, tok, pos, x);

    for (int l = 0; l < NLAYER; l++) {
        ln_kernel<<<BROWS, 256>>>(x, ln1w + l * DMODEL, ln1b + l * DMODEL, h, 0);
        gemm_kernel<false, false, false><<<dim3(3 * DMODEL / 128, BROWS / 128), 256>>>(
            h, qkvw + (size_t)l * 3 * DMODEL * DMODEL, nullptr, nullptr, qkv,
            BROWS, 3 * DMODEL, DMODEL);
        attn_kernel<<<dim3(TSEQ / 64, NHEAD, 2), 256>>>(qkv, att);
        gemm_kernel<false, false, true><<<dim3(DMODEL / 128, BROWS / 128), 256>>>(
            att, outw + (size_t)l * DMODEL * DMODEL, nullptr, x, x,
            BROWS, DMODEL, DMODEL);
        ln_kernel<<<BROWS, 256>>>(x, ln2w + l * DMODEL, ln2b + l * DMODEL, h, 0);
        gemm_kernel<true, true, false><<<dim3(DFFDIM / 128, BROWS / 128), 256>>>(
            h, fc1w + (size_t)l * DFFDIM * DMODEL, fc1b + l * DFFDIM, nullptr, ff,
            BROWS, DFFDIM, DMODEL);
        gemm_kernel<true, false, true><<<dim3(DMODEL / 128, BROWS / 128), 256>>>(
            ff, fc2w + (size_t)l * DMODEL * DFFDIM, fc2b + l * DMODEL, x, x,
            BROWS, DMODEL, DFFDIM);
    }

    ln_kernel<<<MTEXT, 256>>>(x, lnfw, lnfb, hc, 1);
    gemm_kernel<false, false, false><<<dim3(VOCABN / 128, MTEXT / 128), 256>>>(
        hc, headw, nullptr, nullptr, out, MTEXT, VOCABN, DMODEL);
}

// round 7
// speedup vs baseline: 1.9486x; 1.9486x over previous
#include <cuda_runtime.h>
#include <cuda_bf16.h>

// ---------------------------------------------------------------------------
// TinyGPT forward. GEMMs on tensor cores (mma.sync bf16, split-bf16 "bf16x3"
// for fp32-class accuracy). Flash attention + LN/embed in fp32 SIMT.
// B=2, T=2048 (NV=256 vision + 1792 text), D=1024, H=16, DH=64, L=8,
// DFF=4096, VOCAB=32000. Output: fp32 logits [2, 1792, 32000].
// ---------------------------------------------------------------------------

#define TSEQ   2048
#define NVTOK  256
#define TTEXT  1792
#define DMODEL 1024
#define DFFDIM 4096
#define NHEAD  16
#define DHEAD  64
#define NLAYER 8
#define VOCABN 32000
#define BROWS  (2 * TSEQ)    // 4096 total token rows
#define MTEXT  (2 * TTEXT)   // 3584 text rows

// ------------------------- scratch (device globals) ------------------------
__device__ float g_x  [BROWS * DMODEL];
__device__ float g_h  [BROWS * DMODEL];
__device__ float g_qkv[BROWS * 3 * DMODEL];
__device__ float g_att[BROWS * DMODEL];
__device__ float g_ff [BROWS * DFFDIM];
__device__ float g_hc [MTEXT * DMODEL];

// ------------------------------- embedding ---------------------------------
__global__ __launch_bounds__(256)
void embed_kernel(const int* __restrict__ idx, const float* __restrict__ img,
                  const float* __restrict__ tok, const float* __restrict__ pos,
                  float* __restrict__ x)
{
    int i = blockIdx.x * 256 + threadIdx.x;
    int d4 = (i & 255) << 2;
    int t  = (i >> 8) & (TSEQ - 1);
    int b  = i >> 19;

    float4 base;
    if (t < NVTOK) {
        base = *(const float4*)(img + ((size_t)(b * NVTOK + t) * DMODEL) + d4);
    } else {
        int tid = idx[b * TTEXT + (t - NVTOK)];
        base = *(const float4*)(tok + (size_t)tid * DMODEL + d4);
    }
    float4 p = *(const float4*)(pos + (size_t)t * DMODEL + d4);
    base.x += p.x; base.y += p.y; base.z += p.z; base.w += p.w;
    *(float4*)(x + (size_t)(b * TSEQ + t) * DMODEL + d4) = base;
}

// ------------------------------- layernorm ---------------------------------
__global__ __launch_bounds__(256)
void ln_kernel(const float* __restrict__ x, const float* __restrict__ w,
               const float* __restrict__ bias, float* __restrict__ out, int remap)
{
    __shared__ float sh1[8];
    __shared__ float sh2[8];
    int r = blockIdx.x;
    int rin = remap ? ((r / TTEXT) * TSEQ + NVTOK + (r % TTEXT)) : r;
    int tid = threadIdx.x;

    float4 v = *(const float4*)(x + (size_t)rin * DMODEL + (tid << 2));
    float s = v.x + v.y + v.z + v.w;
    #pragma unroll
    for (int o = 16; o > 0; o >>= 1) s += __shfl_xor_sync(0xffffffffu, s, o);
    if ((tid & 31) == 0) sh1[tid >> 5] = s;
    __syncthreads();
    float tot = sh1[0] + sh1[1] + sh1[2] + sh1[3] + sh1[4] + sh1[5] + sh1[6] + sh1[7];
    float mu = tot * (1.0f / DMODEL);

    float d0 = v.x - mu, d1 = v.y - mu, d2 = v.z - mu, d3 = v.w - mu;
    float ss = d0 * d0 + d1 * d1 + d2 * d2 + d3 * d3;
    #pragma unroll
    for (int o = 16; o > 0; o >>= 1) ss += __shfl_xor_sync(0xffffffffu, ss, o);
    if ((tid & 31) == 0) sh2[tid >> 5] = ss;
    __syncthreads();
    float tot2 = sh2[0] + sh2[1] + sh2[2] + sh2[3] + sh2[4] + sh2[5] + sh2[6] + sh2[7];
    float rs = rsqrtf(tot2 * (1.0f / DMODEL) + 1e-5f);

    float4 wv = *(const float4*)(w + (tid << 2));
    float4 bv = *(const float4*)(bias + (tid << 2));
    float4 o4;
    o4.x = d0 * rs * wv.x + bv.x;
    o4.y = d1 * rs * wv.y + bv.y;
    o4.z = d2 * rs * wv.z + bv.z;
    o4.w = d3 * rs * wv.w + bv.w;
    *(float4*)(out + (size_t)r * DMODEL + (tid << 2)) = o4;
}

// ----------------------- tensor-core GEMM (bf16x3) -------------------------
// C[M,N] = A[M,K] @ W[N,K]^T (+bias) (+relu) (+Res), fp32 in/out.
// Inputs split on the fly into hi/lo bf16; product = hi*hi + hi*lo + lo*hi.
// BM=BN=128, BK=32, 256 threads (8 warps), warp tile 64x32 of m16n8k16 mma.
// Requires M%128==0, N%128==0, K%32==0 (true at all call sites).

#define KP 40                       // padded k-stride (bf16 elems) per row
#define BUFE (4 * 128 * KP)         // elems per buffer (Ah,Al,Bh,Bl)

__device__ __forceinline__ void mma16816(float c[4], const unsigned a[4],
                                         const unsigned b[2])
{
    asm volatile(
        "mma.sync.aligned.m16n8k16.row.col.f32.bf16.bf16.f32 "
        "{%0,%1,%2,%3}, {%4,%5,%6,%7}, {%8,%9}, {%0,%1,%2,%3};"
        : "+f"(c[0]), "+f"(c[1]), "+f"(c[2]), "+f"(c[3])
        : "r"(a[0]), "r"(a[1]), "r"(a[2]), "r"(a[3]), "r"(b[0]), "r"(b[1]));
}

__device__ __forceinline__ void split_store4(__nv_bfloat16* hi, __nv_bfloat16* lo,
                                             float4 v)
{
    __nv_bfloat16 h0 = __float2bfloat16(v.x);
    __nv_bfloat16 h1 = __float2bfloat16(v.y);
    __nv_bfloat16 h2 = __float2bfloat16(v.z);
    __nv_bfloat16 h3 = __float2bfloat16(v.w);
    __nv_bfloat16 l0 = __float2bfloat16(v.x - __bfloat162float(h0));
    __nv_bfloat16 l1 = __float2bfloat16(v.y - __bfloat162float(h1));
    __nv_bfloat16 l2 = __float2bfloat16(v.z - __bfloat162float(h2));
    __nv_bfloat16 l3 = __float2bfloat16(v.w - __bfloat162float(h3));
    *(__nv_bfloat162*)(hi)     = __nv_bfloat162(h0, h1);
    *(__nv_bfloat162*)(hi + 2) = __nv_bfloat162(h2, h3);
    *(__nv_bfloat162*)(lo)     = __nv_bfloat162(l0, l1);
    *(__nv_bfloat162*)(lo + 2) = __nv_bfloat162(l2, l3);
}

template<bool BIAS, bool RELU, bool RES>
__global__ __launch_bounds__(256)
void gemm_tc(const float* __restrict__ A, const float* __restrict__ W,
             const float* __restrict__ bias, const float* __restrict__ Res,
             float* __restrict__ C, int M, int N, int K)
{
    extern __shared__ __nv_bfloat16 sm[];
    // buffer b: Ah = sm + b*BUFE, Al = +5120, Bh = +10240, Bl = +15360

    int n0 = blockIdx.x << 7;
    int m0 = blockIdx.y << 7;
    int tid = threadIdx.x;
    int wid = tid >> 5, lane = tid & 31;
    int grp = lane >> 2, tig = lane & 3;
    int wm = (wid >> 2) << 6;       // 0 or 64
    int wn = (wid & 3) << 5;        // 0,32,64,96

    // loader mapping: thread covers rows r0+32i (i=0..3), fixed kc
    int r0 = tid >> 3;
    int kc = (tid & 7) << 2;
    const float* Ag = A + (size_t)(m0 + r0) * K + kc;
    const float* Wg = W + (size_t)(n0 + r0) * K + kc;
    size_t strideA = (size_t)32 * K;

    float acc[4][4][4];
    #pragma unroll
    for (int mi = 0; mi < 4; mi++)
        #pragma unroll
        for (int ni = 0; ni < 4; ni++)
            #pragma unroll
            for (int q = 0; q < 4; q++) acc[mi][ni][q] = 0.f;

    float4 av[4], wv[4];
    // preload tile 0 -> buffer 0
    #pragma unroll
    for (int i = 0; i < 4; i++) {
        av[i] = *(const float4*)(Ag + i * strideA);
        wv[i] = *(const float4*)(Wg + i * strideA);
    }
    {
        __nv_bfloat16* Ah = sm;           __nv_bfloat16* Al = sm + 5120;
        __nv_bfloat16* Bh = sm + 10240;   __nv_bfloat16* Bl = sm + 15360;
        #pragma unroll
        for (int i = 0; i < 4; i++) {
            int off = (r0 + 32 * i) * KP + kc;
            split_store4(Ah + off, Al + off, av[i]);
            split_store4(Bh + off, Bl + off, wv[i]);
        }
    }
    __syncthreads();

    int nk = K >> 5;
    for (int t = 0; t < nk; t++) {
        int cur = t & 1;
        bool more = (t + 1) < nk;
        if (more) {
            int kt = (t + 1) << 5;
            #pragma unroll
            for (int i = 0; i < 4; i++) {
                av[i] = *(const float4*)(Ag + kt + i * strideA);
                wv[i] = *(const float4*)(Wg + kt + i * strideA);
            }
        }

        const __nv_bfloat16* Ah = sm + cur * BUFE;
        const __nv_bfloat16* Al = Ah + 5120;
        const __nv_bfloat16* Bh = Ah + 10240;
        const __nv_bfloat16* Bl = Ah + 15360;

        #pragma unroll
        for (int ks = 0; ks < 32; ks += 16) {
            unsigned ah[4][4], al[4][4], bh[4][2], bl[4][2];
            #pragma unroll
            for (int mi = 0; mi < 4; mi++) {
                int base = (wm + mi * 16 + grp) * KP + ks + 2 * tig;
                ah[mi][0] = *(const unsigned*)(Ah + base);
                ah[mi][1] = *(const unsigned*)(Ah + base + 8 * KP);
                ah[mi][2] = *(const unsigned*)(Ah + base + 8);
                ah[mi][3] = *(const unsigned*)(Ah + base + 8 * KP + 8);
                al[mi][0] = *(const unsigned*)(Al + base);
                al[mi][1] = *(const unsigned*)(Al + base + 8 * KP);
                al[mi][2] = *(const unsigned*)(Al + base + 8);
                al[mi][3] = *(const unsigned*)(Al + base + 8 * KP + 8);
            }
            #pragma unroll
            for (int ni = 0; ni < 4; ni++) {
                int base = (wn + ni * 8 + grp) * KP + ks + 2 * tig;
                bh[ni][0] = *(const unsigned*)(Bh + base);
                bh[ni][1] = *(const unsigned*)(Bh + base + 8);
                bl[ni][0] = *(const unsigned*)(Bl + base);
                bl[ni][1] = *(const unsigned*)(Bl + base + 8);
            }
            #pragma unroll
            for (int mi = 0; mi < 4; mi++)
                #pragma unroll
                for (int ni = 0; ni < 4; ni++) {
                    mma16816(acc[mi][ni], ah[mi], bh[ni]);
                    mma16816(acc[mi][ni], ah[mi], bl[ni]);
                    mma16816(acc[mi][ni], al[mi], bh[ni]);
                }
        }

        if (more) {
            __nv_bfloat16* Ahn = sm + (cur ^ 1) * BUFE;
            __nv_bfloat16* Aln = Ahn + 5120;
            __nv_bfloat16* Bhn = Ahn + 10240;
            __nv_bfloat16* Bln = Ahn + 15360;
            #pragma unroll
            for (int i = 0; i < 4; i++) {
                int off = (r0 + 32 * i) * KP + kc;
                split_store4(Ahn + off, Aln + off, av[i]);
                split_store4(Bhn + off, Bln + off, wv[i]);
            }
        }
        __syncthreads();
    }

    // ------------------------------ epilogue -------------------------------
    #pragma unroll
    for (int mi = 0; mi < 4; mi++) {
        #pragma unroll
        for (int ni = 0; ni < 4; ni++) {
            int row = m0 + wm + mi * 16 + grp;
            int col = n0 + wn + ni * 8 + 2 * tig;
            float2 v0 = make_float2(acc[mi][ni][0], acc[mi][ni][1]);
            float2 v1 = make_float2(acc[mi][ni][2], acc[mi][ni][3]);
            if (BIAS) {
                float2 bv = *(const float2*)(bias + col);
                v0.x += bv.x; v0.y += bv.y; v1.x += bv.x; v1.y += bv.y;
            }
            if (RELU) {
                v0.x = fmaxf(v0.x, 0.f); v0.y = fmaxf(v0.y, 0.f);
                v1.x = fmaxf(v1.x, 0.f); v1.y = fmaxf(v1.y, 0.f);
            }
            if (RES) {
                float2 r0v = *(const float2*)(Res + (size_t)row * N + col);
                float2 r1v = *(const float2*)(Res + (size_t)(row + 8) * N + col);
                v0.x += r0v.x; v0.y += r0v.y; v1.x += r1v.x; v1.y += r1v.y;
            }
            *(float2*)(C + (size_t)row * N + col) = v0;
            *(float2*)(C + (size_t)(row + 8) * N + col) = v1;
        }
    }
}

// ------------------------------- attention ---------------------------------
__global__ __launch_bounds__(256)
void attn_kernel(const float* __restrict__ qkv, float* __restrict__ out)
{
    const int QKVD = 3 * DMODEL;
    int qt0 = blockIdx.x << 6;
    int h = blockIdx.y, b = blockIdx.z;
    int tid = threadIdx.x;
    int tx = tid & 15, ty = tid >> 4;
    int hoff = h * DHEAD;

    __shared__ float Qs[64][68];
    __shared__ float Ks[64][36];
    __shared__ float Vs[32][68];
    __shared__ float Ss[32][68];
    __shared__ float mrow[64], lrow[64], alf[64];

    #pragma unroll
    for (int it = 0; it < 4; it++) {
        int idx = tid + it * 256;
        int row = idx >> 4;
        int d4 = (idx & 15) << 2;
        float4 v = *(const float4*)(qkv + (size_t)(b * TSEQ + qt0 + row) * QKVD + hoff + d4);
        Qs[d4 + 0][row] = v.x; Qs[d4 + 1][row] = v.y;
        Qs[d4 + 2][row] = v.z; Qs[d4 + 3][row] = v.w;
    }
    if (tid < 64) { mrow[tid] = -1e30f; lrow[tid] = 0.f; }

    float o[4][4];
    #pragma unroll
    for (int i = 0; i < 4; i++)
        #pragma unroll
        for (int j = 0; j < 4; j++) o[i][j] = 0.f;

    int ktend = (qt0 >= NVTOK) ? (qt0 + 64) : TSEQ;
    __syncthreads();

    for (int kt0 = 0; kt0 < ktend; kt0 += 32) {
        #pragma unroll
        for (int it = 0; it < 2; it++) {
            int idx = tid + it * 256;
            int row = idx >> 4;
            int d4 = (idx & 15) << 2;
            const float* bp = qkv + (size_t)(b * TSEQ + kt0 + row) * QKVD + hoff + d4;
            float4 kv = *(const float4*)(bp + DMODEL);
            Ks[d4 + 0][row] = kv.x; Ks[d4 + 1][row] = kv.y;
            Ks[d4 + 2][row] = kv.z; Ks[d4 + 3][row] = kv.w;
            float4 vv = *(const float4*)(bp + 2 * DMODEL);
            *(float4*)&Vs[row][d4] = vv;
        }
        __syncthreads();

        float s[4][2];
        #pragma unroll
        for (int i = 0; i < 4; i++) { s[i][0] = 0.f; s[i][1] = 0.f; }
        #pragma unroll
        for (int d = 0; d < 64; d++) {
            float4 a = *(const float4*)&Qs[d][ty << 2];
            float2 bb = *(const float2*)&Ks[d][tx << 1];
            s[0][0] = fmaf(a.x, bb.x, s[0][0]); s[0][1] = fmaf(a.x, bb.y, s[0][1]);
            s[1][0] = fmaf(a.y, bb.x, s[1][0]); s[1][1] = fmaf(a.y, bb.y, s[1][1]);
            s[2][0] = fmaf(a.z, bb.x, s[2][0]); s[2][1] = fmaf(a.z, bb.y, s[2][1]);
            s[3][0] = fmaf(a.w, bb.x, s[3][0]); s[3][1] = fmaf(a.w, bb.y, s[3][1]);
        }
        #pragma unroll
        for (int j = 0; j < 2; j++) {
            int kg = kt0 + (tx << 1) + j;
            #pragma unroll
            for (int i = 0; i < 4; i++) {
                int qg = qt0 + (ty << 2) + i;
                bool ok = (qg < NVTOK) || (kg <= qg);
                Ss[(tx << 1) + j][(ty << 2) + i] = ok ? s[i][j] * 0.125f : -1e30f;
            }
        }
        __syncthreads();

        if (tid < 64) {
            int m = tid;
            float mt = -1e30f;
            #pragma unroll
            for (int n = 0; n < 32; n++) mt = fmaxf(mt, Ss[n][m]);
            float mold = mrow[m];
            float mnew = fmaxf(mold, mt);
            float al = __expf(mold - mnew);
            float sum = 0.f;
            #pragma unroll
            for (int n = 0; n < 32; n++) {
                float p = __expf(Ss[n][m] - mnew);
                Ss[n][m] = p;
                sum += p;
            }
            mrow[m] = mnew;
            lrow[m] = lrow[m] * al + sum;
            alf[m] = al;
        }
        __syncthreads();

        float avx[4];
        #pragma unroll
        for (int i = 0; i < 4; i++) avx[i] = alf[(ty << 2) + i];
        #pragma unroll
        for (int i = 0; i < 4; i++)
            #pragma unroll
            for (int j = 0; j < 4; j++) o[i][j] *= avx[i];
        #pragma unroll
        for (int kk = 0; kk < 32; kk++) {
            float4 p = *(const float4*)&Ss[kk][ty << 2];
            float4 vv = *(const float4*)&Vs[kk][tx << 2];
            float pm[4] = {p.x, p.y, p.z, p.w};
            float vd[4] = {vv.x, vv.y, vv.z, vv.w};
            #pragma unroll
            for (int i = 0; i < 4; i++)
                #pragma unroll
                for (int j = 0; j < 4; j++)
                    o[i][j] = fmaf(pm[i], vd[j], o[i][j]);
        }
        __syncthreads();
    }

    #pragma unroll
    for (int i = 0; i < 4; i++) {
        int qg = qt0 + (ty << 2) + i;
        float inv = 1.f / lrow[(ty << 2) + i];
        float4 r = make_float4(o[i][0] * inv, o[i][1] * inv, o[i][2] * inv, o[i][3] * inv);
        *(float4*)(out + (size_t)(b * TSEQ + qg) * DMODEL + hoff + (tx << 2)) = r;
    }
}

// -------------------------------- launcher ---------------------------------
#define GEMM_SMEM 81920

extern "C" void kernel_launch(void* const* d_in, const int* in_sizes, int n_in,
                              void* d_out, int out_size)
{
    (void)in_sizes; (void)n_in; (void)out_size;
    const int*   idx   = (const int*)  d_in[0];
    const float* img   = (const float*)d_in[1];
    const float* tok   = (const float*)d_in[2];
    const float* pos   = (const float*)d_in[3];
    const float* ln1w  = (const float*)d_in[4];
    const float* ln1b  = (const float*)d_in[5];
    const float* qkvw  = (const float*)d_in[6];
    const float* outw  = (const float*)d_in[7];
    const float* ln2w  = (const float*)d_in[8];
    const float* ln2b  = (const float*)d_in[9];
    const float* fc1w  = (const float*)d_in[10];
    const float* fc1b  = (const float*)d_in[11];
    const float* fc2w  = (const float*)d_in[12];
    const float* fc2b  = (const float*)d_in[13];
    const float* lnfw  = (const float*)d_in[14];
    const float* lnfb  = (const float*)d_in[15];
    const float* headw = (const float*)d_in[16];
    float* out = (float*)d_out;

    float *x, *h, *qkv, *att, *ff, *hc;
    cudaGetSymbolAddress((void**)&x,   g_x);
    cudaGetSymbolAddress((void**)&h,   g_h);
    cudaGetSymbolAddress((void**)&qkv, g_qkv);
    cudaGetSymbolAddress((void**)&att, g_att);
    cudaGetSymbolAddress((void**)&ff,  g_ff);
    cudaGetSymbolAddress((void**)&hc,  g_hc);

    static int attr_done = 0;
    if (!attr_done) {
        cudaFuncSetAttribute(gemm_tc<false, false, false>,
                             cudaFuncAttributeMaxDynamicSharedMemorySize, GEMM_SMEM);
        cudaFuncSetAttribute(gemm_tc<false, false, true>,
                             cudaFuncAttributeMaxDynamicSharedMemorySize, GEMM_SMEM);
        cudaFuncSetAttribute(gemm_tc<true, true, false>,
                             cudaFuncAttributeMaxDynamicSharedMemorySize, GEMM_SMEM);
        cudaFuncSetAttribute(gemm_tc<true, false, true>,
                             cudaFuncAttributeMaxDynamicSharedMemorySize, GEMM_SMEM);
        attr_done = 1;
    }

    embed_kernel<<<4096, 256>>>(idx, img, tok, pos, x);

    for (int l = 0; l < NLAYER; l++) {
        ln_kernel<<<BROWS, 256>>>(x, ln1w + l * DMODEL, ln1b + l * DMODEL, h, 0);
        gemm_tc<false, false, false><<<dim3(3 * DMODEL / 128, BROWS / 128), 256, GEMM_SMEM>>>(
            h, qkvw + (size_t)l * 3 * DMODEL * DMODEL, nullptr, nullptr, qkv,
            BROWS, 3 * DMODEL, DMODEL);
        attn_kernel<<<dim3(TSEQ / 64, NHEAD, 2), 256>>>(qkv, att);
        gemm_tc<false, false, true><<<dim3(DMODEL / 128, BROWS / 128), 256, GEMM_SMEM>>>(
            att, outw + (size_t)l * DMODEL * DMODEL, nullptr, x, x,
            BROWS, DMODEL, DMODEL);
        ln_kernel<<<BROWS, 256>>>(x, ln2w + l * DMODEL, ln2b + l * DMODEL, h, 0);
        gemm_tc<true, true, false><<<dim3(DFFDIM / 128, BROWS / 128), 256, GEMM_SMEM>>>(
            h, fc1w + (size_t)l * DFFDIM * DMODEL, fc1b + l * DFFDIM, nullptr, ff,
            BROWS, DFFDIM, DMODEL);
        gemm_tc<true, false, true><<<dim3(DMODEL / 128, BROWS / 128), 256, GEMM_SMEM>>>(
            ff, fc2w + (size_t)l * DMODEL * DFFDIM, fc2b + l * DMODEL, x, x,
            BROWS, DMODEL, DFFDIM);
    }

    ln_kernel<<<MTEXT, 256>>>(x, lnfw, lnfb, hc, 1);
    gemm_tc<false, false, false><<<dim3(VOCABN / 128, MTEXT / 128), 256, GEMM_SMEM>>>(
        hc, headw, nullptr, nullptr, out, MTEXT, VOCABN, DMODEL);
}

// round 8
// speedup vs baseline: 2.4933x; 1.2796x over previous
#include <cuda_runtime.h>
#include <cuda_bf16.h>

// ---------------------------------------------------------------------------
// TinyGPT forward. GEMMs + attention on tensor cores (mma.sync bf16 with
// split-bf16 "bf16x3" accuracy). LN/embed in fp32 SIMT.
// B=2, T=2048 (NV=256 vision + 1792 text), D=1024, H=16, DH=64, L=8,
// DFF=4096, VOCAB=32000. Output: fp32 logits [2, 1792, 32000].
// ---------------------------------------------------------------------------

#define TSEQ   2048
#define NVTOK  256
#define TTEXT  1792
#define DMODEL 1024
#define DFFDIM 4096
#define NHEAD  16
#define DHEAD  64
#define NLAYER 8
#define VOCABN 32000
#define BROWS  (2 * TSEQ)
#define MTEXT  (2 * TTEXT)

// ------------------------- scratch (device globals) ------------------------
__device__ float g_x  [BROWS * DMODEL];
__device__ float g_h  [BROWS * DMODEL];
__device__ float g_qkv[BROWS * 3 * DMODEL];
__device__ float g_att[BROWS * DMODEL];
__device__ float g_ff [BROWS * DFFDIM];
__device__ float g_hc [MTEXT * DMODEL];

// ------------------------------ helpers ------------------------------------
__device__ __forceinline__ void mma16816(float c[4], const unsigned a[4],
                                         const unsigned b[2])
{
    asm volatile(
        "mma.sync.aligned.m16n8k16.row.col.f32.bf16.bf16.f32 "
        "{%0,%1,%2,%3}, {%4,%5,%6,%7}, {%8,%9}, {%0,%1,%2,%3};"
        : "+f"(c[0]), "+f"(c[1]), "+f"(c[2]), "+f"(c[3])
        : "r"(a[0]), "r"(a[1]), "r"(a[2]), "r"(a[3]), "r"(b[0]), "r"(b[1]));
}

// split two floats into hi/lo bf16x2 packs (hi = bf16(x), lo = bf16(x - hi))
__device__ __forceinline__ void split2(float x, float y, unsigned& hi, unsigned& lo)
{
    __nv_bfloat16 hx = __float2bfloat16(x);
    __nv_bfloat16 hy = __float2bfloat16(y);
    __nv_bfloat162 H(hx, hy);
    hi = *(unsigned*)&H;
    __nv_bfloat162 L = __floats2bfloat162_rn(x - __bfloat162float(hx),
                                             y - __bfloat162float(hy));
    lo = *(unsigned*)&L;
}

// ------------------------------- embedding ---------------------------------
__global__ __launch_bounds__(256)
void embed_kernel(const int* __restrict__ idx, const float* __restrict__ img,
                  const float* __restrict__ tok, const float* __restrict__ pos,
                  float* __restrict__ x)
{
    int i = blockIdx.x * 256 + threadIdx.x;
    int d4 = (i & 255) << 2;
    int t  = (i >> 8) & (TSEQ - 1);
    int b  = i >> 19;

    float4 base;
    if (t < NVTOK) {
        base = *(const float4*)(img + ((size_t)(b * NVTOK + t) * DMODEL) + d4);
    } else {
        int tid = idx[b * TTEXT + (t - NVTOK)];
        base = *(const float4*)(tok + (size_t)tid * DMODEL + d4);
    }
    float4 p = *(const float4*)(pos + (size_t)t * DMODEL + d4);
    base.x += p.x; base.y += p.y; base.z += p.z; base.w += p.w;
    *(float4*)(x + (size_t)(b * TSEQ + t) * DMODEL + d4) = base;
}

// ------------------------------- layernorm ---------------------------------
__global__ __launch_bounds__(256)
void ln_kernel(const float* __restrict__ x, const float* __restrict__ w,
               const float* __restrict__ bias, float* __restrict__ out, int remap)
{
    __shared__ float sh1[8];
    __shared__ float sh2[8];
    int r = blockIdx.x;
    int rin = remap ? ((r / TTEXT) * TSEQ + NVTOK + (r % TTEXT)) : r;
    int tid = threadIdx.x;

    float4 v = *(const float4*)(x + (size_t)rin * DMODEL + (tid << 2));
    float s = v.x + v.y + v.z + v.w;
    #pragma unroll
    for (int o = 16; o > 0; o >>= 1) s += __shfl_xor_sync(0xffffffffu, s, o);
    if ((tid & 31) == 0) sh1[tid >> 5] = s;
    __syncthreads();
    float tot = sh1[0] + sh1[1] + sh1[2] + sh1[3] + sh1[4] + sh1[5] + sh1[6] + sh1[7];
    float mu = tot * (1.0f / DMODEL);

    float d0 = v.x - mu, d1 = v.y - mu, d2 = v.z - mu, d3 = v.w - mu;
    float ss = d0 * d0 + d1 * d1 + d2 * d2 + d3 * d3;
    #pragma unroll
    for (int o = 16; o > 0; o >>= 1) ss += __shfl_xor_sync(0xffffffffu, ss, o);
    if ((tid & 31) == 0) sh2[tid >> 5] = ss;
    __syncthreads();
    float tot2 = sh2[0] + sh2[1] + sh2[2] + sh2[3] + sh2[4] + sh2[5] + sh2[6] + sh2[7];
    float rs = rsqrtf(tot2 * (1.0f / DMODEL) + 1e-5f);

    float4 wv = *(const float4*)(w + (tid << 2));
    float4 bv = *(const float4*)(bias + (tid << 2));
    float4 o4;
    o4.x = d0 * rs * wv.x + bv.x;
    o4.y = d1 * rs * wv.y + bv.y;
    o4.z = d2 * rs * wv.z + bv.z;
    o4.w = d3 * rs * wv.w + bv.w;
    *(float4*)(out + (size_t)r * DMODEL + (tid << 2)) = o4;
}

// ----------------------- tensor-core GEMM (bf16x3) -------------------------
#define KP 40
#define BUFE (4 * 128 * KP)

__device__ __forceinline__ void split_store4(__nv_bfloat16* hi, __nv_bfloat16* lo,
                                             float4 v)
{
    __nv_bfloat16 h0 = __float2bfloat16(v.x);
    __nv_bfloat16 h1 = __float2bfloat16(v.y);
    __nv_bfloat16 h2 = __float2bfloat16(v.z);
    __nv_bfloat16 h3 = __float2bfloat16(v.w);
    __nv_bfloat16 l0 = __float2bfloat16(v.x - __bfloat162float(h0));
    __nv_bfloat16 l1 = __float2bfloat16(v.y - __bfloat162float(h1));
    __nv_bfloat16 l2 = __float2bfloat16(v.z - __bfloat162float(h2));
    __nv_bfloat16 l3 = __float2bfloat16(v.w - __bfloat162float(h3));
    *(__nv_bfloat162*)(hi)     = __nv_bfloat162(h0, h1);
    *(__nv_bfloat162*)(hi + 2) = __nv_bfloat162(h2, h3);
    *(__nv_bfloat162*)(lo)     = __nv_bfloat162(l0, l1);
    *(__nv_bfloat162*)(lo + 2) = __nv_bfloat162(l2, l3);
}

template<bool BIAS, bool RELU, bool RES>
__global__ __launch_bounds__(256)
void gemm_tc(const float* __restrict__ A, const float* __restrict__ W,
             const float* __restrict__ bias, const float* __restrict__ Res,
             float* __restrict__ C, int M, int N, int K)
{
    extern __shared__ __nv_bfloat16 sm[];

    int n0 = blockIdx.x << 7;
    int m0 = blockIdx.y << 7;
    int tid = threadIdx.x;
    int wid = tid >> 5, lane = tid & 31;
    int grp = lane >> 2, tig = lane & 3;
    int wm = (wid >> 2) << 6;
    int wn = (wid & 3) << 5;

    int r0 = tid >> 3;
    int kc = (tid & 7) << 2;
    const float* Ag = A + (size_t)(m0 + r0) * K + kc;
    const float* Wg = W + (size_t)(n0 + r0) * K + kc;
    size_t strideA = (size_t)32 * K;

    float acc[4][4][4];
    #pragma unroll
    for (int mi = 0; mi < 4; mi++)
        #pragma unroll
        for (int ni = 0; ni < 4; ni++)
            #pragma unroll
            for (int q = 0; q < 4; q++) acc[mi][ni][q] = 0.f;

    float4 av[4], wv[4];
    #pragma unroll
    for (int i = 0; i < 4; i++) {
        av[i] = *(const float4*)(Ag + i * strideA);
        wv[i] = *(const float4*)(Wg + i * strideA);
    }
    {
        __nv_bfloat16* Ah = sm;           __nv_bfloat16* Al = sm + 5120;
        __nv_bfloat16* Bh = sm + 10240;   __nv_bfloat16* Bl = sm + 15360;
        #pragma unroll
        for (int i = 0; i < 4; i++) {
            int off = (r0 + 32 * i) * KP + kc;
            split_store4(Ah + off, Al + off, av[i]);
            split_store4(Bh + off, Bl + off, wv[i]);
        }
    }
    __syncthreads();

    int nk = K >> 5;
    for (int t = 0; t < nk; t++) {
        int cur = t & 1;
        bool more = (t + 1) < nk;
        if (more) {
            int kt = (t + 1) << 5;
            #pragma unroll
            for (int i = 0; i < 4; i++) {
                av[i] = *(const float4*)(Ag + kt + i * strideA);
                wv[i] = *(const float4*)(Wg + kt + i * strideA);
            }
        }

        const __nv_bfloat16* Ah = sm + cur * BUFE;
        const __nv_bfloat16* Al = Ah + 5120;
        const __nv_bfloat16* Bh = Ah + 10240;
        const __nv_bfloat16* Bl = Ah + 15360;

        #pragma unroll
        for (int ks = 0; ks < 32; ks += 16) {
            unsigned ah[4][4], al[4][4], bh[4][2], bl[4][2];
            #pragma unroll
            for (int mi = 0; mi < 4; mi++) {
                int base = (wm + mi * 16 + grp) * KP + ks + 2 * tig;
                ah[mi][0] = *(const unsigned*)(Ah + base);
                ah[mi][1] = *(const unsigned*)(Ah + base + 8 * KP);
                ah[mi][2] = *(const unsigned*)(Ah + base + 8);
                ah[mi][3] = *(const unsigned*)(Ah + base + 8 * KP + 8);
                al[mi][0] = *(const unsigned*)(Al + base);
                al[mi][1] = *(const unsigned*)(Al + base + 8 * KP);
                al[mi][2] = *(const unsigned*)(Al + base + 8);
                al[mi][3] = *(const unsigned*)(Al + base + 8 * KP + 8);
            }
            #pragma unroll
            for (int ni = 0; ni < 4; ni++) {
                int base = (wn + ni * 8 + grp) * KP + ks + 2 * tig;
                bh[ni][0] = *(const unsigned*)(Bh + base);
                bh[ni][1] = *(const unsigned*)(Bh + base + 8);
                bl[ni][0] = *(const unsigned*)(Bl + base);
                bl[ni][1] = *(const unsigned*)(Bl + base + 8);
            }
            #pragma unroll
            for (int mi = 0; mi < 4; mi++)
                #pragma unroll
                for (int ni = 0; ni < 4; ni++) {
                    mma16816(acc[mi][ni], ah[mi], bh[ni]);
                    mma16816(acc[mi][ni], ah[mi], bl[ni]);
                    mma16816(acc[mi][ni], al[mi], bh[ni]);
                }
        }

        if (more) {
            __nv_bfloat16* Ahn = sm + (cur ^ 1) * BUFE;
            __nv_bfloat16* Aln = Ahn + 5120;
            __nv_bfloat16* Bhn = Ahn + 10240;
            __nv_bfloat16* Bln = Ahn + 15360;
            #pragma unroll
            for (int i = 0; i < 4; i++) {
                int off = (r0 + 32 * i) * KP + kc;
                split_store4(Ahn + off, Aln + off, av[i]);
                split_store4(Bhn + off, Bln + off, wv[i]);
            }
        }
        __syncthreads();
    }

    #pragma unroll
    for (int mi = 0; mi < 4; mi++) {
        #pragma unroll
        for (int ni = 0; ni < 4; ni++) {
            int row = m0 + wm + mi * 16 + grp;
            int col = n0 + wn + ni * 8 + 2 * tig;
            float2 v0 = make_float2(acc[mi][ni][0], acc[mi][ni][1]);
            float2 v1 = make_float2(acc[mi][ni][2], acc[mi][ni][3]);
            if (BIAS) {
                float2 bv = *(const float2*)(bias + col);
                v0.x += bv.x; v0.y += bv.y; v1.x += bv.x; v1.y += bv.y;
            }
            if (RELU) {
                v0.x = fmaxf(v0.x, 0.f); v0.y = fmaxf(v0.y, 0.f);
                v1.x = fmaxf(v1.x, 0.f); v1.y = fmaxf(v1.y, 0.f);
            }
            if (RES) {
                float2 r0v = *(const float2*)(Res + (size_t)row * N + col);
                float2 r1v = *(const float2*)(Res + (size_t)(row + 8) * N + col);
                v0.x += r0v.x; v0.y += r0v.y; v1.x += r1v.x; v1.y += r1v.y;
            }
            *(float2*)(C + (size_t)row * N + col) = v0;
            *(float2*)(C + (size_t)(row + 8) * N + col) = v1;
        }
    }
}

// ------------------- tensor-core flash attention (bf16x3) ------------------
// Block = 128 threads (4 warps). Warp w owns q-rows [qt0+16w, qt0+16w+16),
// full 64-key tile width -> softmax stats reduce within a lane-quad only.
// S stays in registers; its mma C-fragment is re-packed as the A-fragment
// of P@V. Q.K and P.V both use hi/lo split (3 mma) for fp32-class accuracy.
#define AKP 72   // padded row length (bf16) for K/V smem tiles

__global__ __launch_bounds__(128)
void attn_tc(const float* __restrict__ qkv, float* __restrict__ out)
{
    const int QKVD = 3 * DMODEL;
    int qt0 = blockIdx.x << 6;
    int h = blockIdx.y, b = blockIdx.z;
    int tid = threadIdx.x;
    int warp = tid >> 5, lane = tid & 31;
    int grp = lane >> 2, tig = lane & 3;
    int wm = warp << 4;
    int hoff = h * DHEAD;

    __shared__ __nv_bfloat16 Ksh[64][AKP], Ksl[64][AKP];
    __shared__ __nv_bfloat16 Vth[64][AKP], Vtl[64][AKP];

    // ---- Q fragments (pre-scaled by 1/sqrt(DH) = 0.125, exact), hi/lo ----
    unsigned qh[4][4], ql[4][4];
    {
        const float* Q0 = qkv + (size_t)(b * TSEQ + qt0 + wm + grp) * QKVD + hoff;
        const float* Q1 = Q0 + (size_t)8 * QKVD;
        #pragma unroll
        for (int c = 0; c < 4; c++) {
            int k0 = 16 * c + 2 * tig;
            float2 f0 = *(const float2*)(Q0 + k0);
            float2 f1 = *(const float2*)(Q1 + k0);
            float2 f2 = *(const float2*)(Q0 + k0 + 8);
            float2 f3 = *(const float2*)(Q1 + k0 + 8);
            split2(f0.x * 0.125f, f0.y * 0.125f, qh[c][0], ql[c][0]);
            split2(f1.x * 0.125f, f1.y * 0.125f, qh[c][1], ql[c][1]);
            split2(f2.x * 0.125f, f2.y * 0.125f, qh[c][2], ql[c][2]);
            split2(f3.x * 0.125f, f3.y * 0.125f, qh[c][3], ql[c][3]);
        }
    }

    float oc[8][4];
    #pragma unroll
    for (int dt = 0; dt < 8; dt++)
        #pragma unroll
        for (int q = 0; q < 4; q++) oc[dt][q] = 0.f;
    float m0 = -1e30f, m1 = -1e30f, l0 = 0.f, l1 = 0.f;

    int qg0 = qt0 + wm + grp, qg1 = qg0 + 8;
    int ktend = (qt0 >= NVTOK) ? (qt0 + 64) : TSEQ;

    for (int kt0 = 0; kt0 < ktend; kt0 += 64) {
        // ---- load K/V tile (64 keys x 64 dims), split, V transposed ----
        #pragma unroll
        for (int i = 0; i < 8; i++) {
            int idx = tid + (i << 7);
            int key = idx >> 4, d4 = (idx & 15) << 2;
            const float* bp = qkv + (size_t)(b * TSEQ + kt0 + key) * QKVD + hoff + d4;
            float4 kv = *(const float4*)(bp + DMODEL);
            split_store4(&Ksh[key][d4], &Ksl[key][d4], kv);
            float4 vv = *(const float4*)(bp + 2 * DMODEL);
            float vf[4] = {vv.x, vv.y, vv.z, vv.w};
            #pragma unroll
            for (int j = 0; j < 4; j++) {
                __nv_bfloat16 hi = __float2bfloat16(vf[j]);
                Vth[d4 + j][key] = hi;
                Vtl[d4 + j][key] = __float2bfloat16(vf[j] - __bfloat162float(hi));
            }
        }
        __syncthreads();

        // ---- S = Q @ K^T (scaled) ----
        float sc[8][4];
        #pragma unroll
        for (int nt = 0; nt < 8; nt++)
            #pragma unroll
            for (int q = 0; q < 4; q++) sc[nt][q] = 0.f;

        #pragma unroll
        for (int nt = 0; nt < 8; nt++) {
            int krow = nt * 8 + grp;
            #pragma unroll
            for (int c = 0; c < 4; c++) {
                int k0 = 16 * c + 2 * tig;
                unsigned bh[2], bl[2];
                bh[0] = *(const unsigned*)&Ksh[krow][k0];
                bh[1] = *(const unsigned*)&Ksh[krow][k0 + 8];
                bl[0] = *(const unsigned*)&Ksl[krow][k0];
                bl[1] = *(const unsigned*)&Ksl[krow][k0 + 8];
                mma16816(sc[nt], qh[c], bh);
                mma16816(sc[nt], qh[c], bl);
                mma16816(sc[nt], ql[c], bh);
            }
        }

        // ---- mask ----
        #pragma unroll
        for (int nt = 0; nt < 8; nt++) {
            int kg0 = kt0 + nt * 8 + 2 * tig;
            int kg1 = kg0 + 1;
            if (!((qg0 < NVTOK) || (kg0 <= qg0))) sc[nt][0] = -1e30f;
            if (!((qg0 < NVTOK) || (kg1 <= qg0))) sc[nt][1] = -1e30f;
            if (!((qg1 < NVTOK) || (kg0 <= qg1))) sc[nt][2] = -1e30f;
            if (!((qg1 < NVTOK) || (kg1 <= qg1))) sc[nt][3] = -1e30f;
        }

        // ---- online softmax (rows live in a lane-quad) ----
        float mx0 = -1e30f, mx1 = -1e30f;
        #pragma unroll
        for (int nt = 0; nt < 8; nt++) {
            mx0 = fmaxf(mx0, fmaxf(sc[nt][0], sc[nt][1]));
            mx1 = fmaxf(mx1, fmaxf(sc[nt][2], sc[nt][3]));
        }
        mx0 = fmaxf(mx0, __shfl_xor_sync(0xffffffffu, mx0, 1));
        mx0 = fmaxf(mx0, __shfl_xor_sync(0xffffffffu, mx0, 2));
        mx1 = fmaxf(mx1, __shfl_xor_sync(0xffffffffu, mx1, 1));
        mx1 = fmaxf(mx1, __shfl_xor_sync(0xffffffffu, mx1, 2));
        float mn0 = fmaxf(m0, mx0), mn1 = fmaxf(m1, mx1);
        float al0 = __expf(m0 - mn0), al1 = __expf(m1 - mn1);
        m0 = mn0; m1 = mn1;

        float sum0 = 0.f, sum1 = 0.f;
        #pragma unroll
        for (int nt = 0; nt < 8; nt++) {
            sc[nt][0] = __expf(sc[nt][0] - mn0); sum0 += sc[nt][0];
            sc[nt][1] = __expf(sc[nt][1] - mn0); sum0 += sc[nt][1];
            sc[nt][2] = __expf(sc[nt][2] - mn1); sum1 += sc[nt][2];
            sc[nt][3] = __expf(sc[nt][3] - mn1); sum1 += sc[nt][3];
        }
        sum0 += __shfl_xor_sync(0xffffffffu, sum0, 1);
        sum0 += __shfl_xor_sync(0xffffffffu, sum0, 2);
        sum1 += __shfl_xor_sync(0xffffffffu, sum1, 1);
        sum1 += __shfl_xor_sync(0xffffffffu, sum1, 2);
        l0 = l0 * al0 + sum0;
        l1 = l1 * al1 + sum1;

        #pragma unroll
        for (int dt = 0; dt < 8; dt++) {
            oc[dt][0] *= al0; oc[dt][1] *= al0;
            oc[dt][2] *= al1; oc[dt][3] *= al1;
        }

        // ---- re-pack P (C-frag -> A-frag), hi/lo ----
        unsigned ph[4][4], pl[4][4];
        #pragma unroll
        for (int c = 0; c < 4; c++) {
            split2(sc[2 * c][0],     sc[2 * c][1],     ph[c][0], pl[c][0]);
            split2(sc[2 * c][2],     sc[2 * c][3],     ph[c][1], pl[c][1]);
            split2(sc[2 * c + 1][0], sc[2 * c + 1][1], ph[c][2], pl[c][2]);
            split2(sc[2 * c + 1][2], sc[2 * c + 1][3], ph[c][3], pl[c][3]);
        }

        // ---- O += P @ V ----
        #pragma unroll
        for (int dt = 0; dt < 8; dt++) {
            int drow = dt * 8 + grp;
            #pragma unroll
            for (int c = 0; c < 4; c++) {
                int k0 = 16 * c + 2 * tig;
                unsigned bh[2], bl[2];
                bh[0] = *(const unsigned*)&Vth[drow][k0];
                bh[1] = *(const unsigned*)&Vth[drow][k0 + 8];
                bl[0] = *(const unsigned*)&Vtl[drow][k0];
                bl[1] = *(const unsigned*)&Vtl[drow][k0 + 8];
                mma16816(oc[dt], ph[c], bh);
                mma16816(oc[dt], ph[c], bl);
                mma16816(oc[dt], pl[c], bh);
            }
        }
        __syncthreads();
    }

    // ---- epilogue ----
    float inv0 = 1.f / l0, inv1 = 1.f / l1;
    float* o0 = out + (size_t)(b * TSEQ + qg0) * DMODEL + hoff;
    float* o1 = out + (size_t)(b * TSEQ + qg1) * DMODEL + hoff;
    #pragma unroll
    for (int dt = 0; dt < 8; dt++) {
        int dcol = dt * 8 + 2 * tig;
        *(float2*)(o0 + dcol) = make_float2(oc[dt][0] * inv0, oc[dt][1] * inv0);
        *(float2*)(o1 + dcol) = make_float2(oc[dt][2] * inv1, oc[dt][3] * inv1);
    }
}

// -------------------------------- launcher ---------------------------------
#define GEMM_SMEM 81920

extern "C" void kernel_launch(void* const* d_in, const int* in_sizes, int n_in,
                              void* d_out, int out_size)
{
    (void)in_sizes; (void)n_in; (void)out_size;
    const int*   idx   = (const int*)  d_in[0];
    const float* img   = (const float*)d_in[1];
    const float* tok   = (const float*)d_in[2];
    const float* pos   = (const float*)d_in[3];
    const float* ln1w  = (const float*)d_in[4];
    const float* ln1b  = (const float*)d_in[5];
    const float* qkvw  = (const float*)d_in[6];
    const float* outw  = (const float*)d_in[7];
    const float* ln2w  = (const float*)d_in[8];
    const float* ln2b  = (const float*)d_in[9];
    const float* fc1w  = (const float*)d_in[10];
    const float* fc1b  = (const float*)d_in[11];
    const float* fc2w  = (const float*)d_in[12];
    const float* fc2b  = (const float*)d_in[13];
    const float* lnfw  = (const float*)d_in[14];
    const float* lnfb  = (const float*)d_in[15];
    const float* headw = (const float*)d_in[16];
    float* out = (float*)d_out;

    float *x, *h, *qkv, *att, *ff, *hc;
    cudaGetSymbolAddress((void**)&x,   g_x);
    cudaGetSymbolAddress((void**)&h,   g_h);
    cudaGetSymbolAddress((void**)&qkv, g_qkv);
    cudaGetSymbolAddress((void**)&att, g_att);
    cudaGetSymbolAddress((void**)&ff,  g_ff);
    cudaGetSymbolAddress((void**)&hc,  g_hc);

    static int attr_done = 0;
    if (!attr_done) {
        cudaFuncSetAttribute(gemm_tc<false, false, false>,
                             cudaFuncAttributeMaxDynamicSharedMemorySize, GEMM_SMEM);
        cudaFuncSetAttribute(gemm_tc<false, false, true>,
                             cudaFuncAttributeMaxDynamicSharedMemorySize, GEMM_SMEM);
        cudaFuncSetAttribute(gemm_tc<true, true, false>,
                             cudaFuncAttributeMaxDynamicSharedMemorySize, GEMM_SMEM);
        cudaFuncSetAttribute(gemm_tc<true, false, true>,
                             cudaFuncAttributeMaxDynamicSharedMemorySize, GEMM_SMEM);
        attr_done = 1;
    }

    embed_kernel<<<4096, 256>>>(idx, img, tok, pos, x);

    for (int l = 0; l < NLAYER; l++) {
        ln_kernel<<<BROWS, 256>>>(x, ln1w + l * DMODEL, ln1b + l * DMODEL, h, 0);
        gemm_tc<false, false, false><<<dim3(3 * DMODEL / 128, BROWS / 128), 256, GEMM_SMEM>>>(
            h, qkvw + (size_t)l * 3 * DMODEL * DMODEL, nullptr, nullptr, qkv,
            BROWS, 3 * DMODEL, DMODEL);
        attn_tc<<<dim3(TSEQ / 64, NHEAD, 2), 128>>>(qkv, att);
        gemm_tc<false, false, true><<<dim3(DMODEL / 128, BROWS / 128), 256, GEMM_SMEM>>>(
            att, outw + (size_t)l * DMODEL * DMODEL, nullptr, x, x,
            BROWS, DMODEL, DMODEL);
        ln_kernel<<<BROWS, 256>>>(x, ln2w + l * DMODEL, ln2b + l * DMODEL, h, 0);
        gemm_tc<true, true, false><<<dim3(DFFDIM / 128, BROWS / 128), 256, GEMM_SMEM>>>(
            h, fc1w + (size_t)l * DFFDIM * DMODEL, fc1b + l * DFFDIM, nullptr, ff,
            BROWS, DFFDIM, DMODEL);
        gemm_tc<true, false, true><<<dim3(DMODEL / 128, BROWS / 128), 256, GEMM_SMEM>>>(
            ff, fc2w + (size_t)l * DMODEL * DFFDIM, fc2b + l * DMODEL, x, x,
            BROWS, DMODEL, DFFDIM);
    }

    ln_kernel<<<MTEXT, 256>>>(x, lnfw, lnfb, hc, 1);
    gemm_tc<false, false, false><<<dim3(VOCABN / 128, MTEXT / 128), 256, GEMM_SMEM>>>(
        hc, headw, nullptr, nullptr, out, MTEXT, VOCABN, DMODEL);
}